// round 1
// baseline (speedup 1.0000x reference)
#include <cuda_runtime.h>
#include <math.h>

// Problem constants
#define Bc   4
#define Sc   2048
#define Dc   2048
#define Hc   16
#define DKc  128
#define Mc   (Bc * Sc)   // 8192 rows

// Scratch buffers (allocation-free rule: __device__ globals)
__device__ float g_q[(size_t)Mc * Dc];
__device__ float g_k[(size_t)Mc * Dc];
__device__ float g_v[(size_t)Mc * Dc];
__device__ float g_att[(size_t)Mc * Dc];

// ---------------------------------------------------------------------------
// C[M,N] = A[M,K] @ W[N,K]^T + bias[N]   (torch Linear semantics)
// 128x128 tile, BK=8, 256 threads, 8x8 micro-tile per thread.
// M,N multiples of 128; K multiple of 8 (holds for all our shapes).
// ---------------------------------------------------------------------------
__global__ __launch_bounds__(256, 2)
void gemm_nt_bias(const float* __restrict__ A, const float* __restrict__ W,
                  const float* __restrict__ bias, float* __restrict__ C,
                  int M, int N, int K)
{
    __shared__ float As[8][128];
    __shared__ float Bs[8][128];

    const int tid = threadIdx.x;
    const int bm  = blockIdx.y * 128;
    const int bn  = blockIdx.x * 128;

    // loader mapping: 2 threads per row, each loads a float4 of K
    const int lr = tid >> 1;          // 0..127 row within tile
    const int lk = (tid & 1) << 2;    // 0 or 4

    // compute mapping
    const int tx = tid & 15;          // col group (x8)
    const int ty = tid >> 4;          // row group (x8)

    const float* Ap = A + (size_t)(bm + lr) * K + lk;
    const float* Wp = W + (size_t)(bn + lr) * K + lk;

    float acc[8][8];
#pragma unroll
    for (int i = 0; i < 8; ++i)
#pragma unroll
        for (int j = 0; j < 8; ++j) acc[i][j] = 0.f;

    for (int k0 = 0; k0 < K; k0 += 8) {
        float4 av = *(const float4*)(Ap + k0);
        float4 wv = *(const float4*)(Wp + k0);
        __syncthreads();   // previous iteration's compute done
        As[lk + 0][lr] = av.x; As[lk + 1][lr] = av.y;
        As[lk + 2][lr] = av.z; As[lk + 3][lr] = av.w;
        Bs[lk + 0][lr] = wv.x; Bs[lk + 1][lr] = wv.y;
        Bs[lk + 2][lr] = wv.z; Bs[lk + 3][lr] = wv.w;
        __syncthreads();

#pragma unroll
        for (int kk = 0; kk < 8; ++kk) {
            float a[8], b[8];
            *(float4*)(a)     = *(const float4*)(&As[kk][ty * 8]);
            *(float4*)(a + 4) = *(const float4*)(&As[kk][ty * 8 + 4]);
            *(float4*)(b)     = *(const float4*)(&Bs[kk][tx * 8]);
            *(float4*)(b + 4) = *(const float4*)(&Bs[kk][tx * 8 + 4]);
#pragma unroll
            for (int i = 0; i < 8; ++i)
#pragma unroll
                for (int j = 0; j < 8; ++j)
                    acc[i][j] = fmaf(a[i], b[j], acc[i][j]);
        }
    }

#pragma unroll
    for (int i = 0; i < 8; ++i) {
        const int row = bm + ty * 8 + i;
#pragma unroll
        for (int j0 = 0; j0 < 8; j0 += 4) {
            const int col = bn + tx * 8 + j0;
            float4 o;
            o.x = acc[i][j0 + 0] + bias[col + 0];
            o.y = acc[i][j0 + 1] + bias[col + 1];
            o.z = acc[i][j0 + 2] + bias[col + 2];
            o.w = acc[i][j0 + 3] + bias[col + 3];
            *(float4*)(&C[(size_t)row * N + col]) = o;
        }
    }
}

// ---------------------------------------------------------------------------
// Flash attention, fp32, per (b, h, q-tile). BQ=64, BKV=64, DK=128.
// Q/K stored d-major (transposed) in smem so score compute is SGEMM-style.
// Online softmax; P staged q-major in smem for the P@V GEMM.
// ---------------------------------------------------------------------------
#define PST 68   // Ps row stride (64 keys + pad, multiple of 4 for float4)
#define FLASH_SMEM ((3 * 128 * 64 + 64 * PST) * (int)sizeof(float))  // 115712 B

__global__ __launch_bounds__(256, 1)
void flash_kernel(const float* __restrict__ Q, const float* __restrict__ K,
                  const float* __restrict__ V, float* __restrict__ O)
{
    extern __shared__ float sm[];
    float* Qt = sm;                 // [128 d][64 q]
    float* Kt = sm + 128 * 64;      // [128 d][64 k]
    float* Vs = sm + 2 * 128 * 64;  // [64 k][128 d]
    float* Ps = sm + 3 * 128 * 64;  // [64 q][PST]

    const int tid = threadIdx.x;
    const int tx  = tid & 15;       // key-group (scores) / d-group (output)
    const int ty  = tid >> 4;       // query-group
    const int q0  = blockIdx.x * 64;
    const int h   = blockIdx.y;
    const int b   = blockIdx.z;
    const size_t base = (size_t)b * Sc * Dc + (size_t)h * DKc;
    const float scale = 0.08838834764831845f;  // 1/sqrt(128)

    // tile loader mapping: 32 float4-columns x 8 row-slices
    const int f  = tid & 31;
    const int r0 = (tid >> 5) * 8;

    // Load Q tile transposed (persistent across KV loop)
#pragma unroll
    for (int rr = 0; rr < 8; ++rr) {
        const int row = r0 + rr;
        float4 q4 = *(const float4*)(Q + base + (size_t)(q0 + row) * Dc + f * 4);
        Qt[(f * 4 + 0) * 64 + row] = q4.x;
        Qt[(f * 4 + 1) * 64 + row] = q4.y;
        Qt[(f * 4 + 2) * 64 + row] = q4.z;
        Qt[(f * 4 + 3) * 64 + row] = q4.w;
    }

    float m_i[4], l_i[4], o[4][8];
#pragma unroll
    for (int i = 0; i < 4; ++i) {
        m_i[i] = -1e30f;
        l_i[i] = 0.f;
#pragma unroll
        for (int j = 0; j < 8; ++j) o[i][j] = 0.f;
    }

    for (int kv0 = 0; kv0 < Sc; kv0 += 64) {
        __syncthreads();  // previous tile's compute (Kt/Vs/Ps reads) done
#pragma unroll
        for (int rr = 0; rr < 8; ++rr) {
            const int row = r0 + rr;
            float4 k4 = *(const float4*)(K + base + (size_t)(kv0 + row) * Dc + f * 4);
            Kt[(f * 4 + 0) * 64 + row] = k4.x;
            Kt[(f * 4 + 1) * 64 + row] = k4.y;
            Kt[(f * 4 + 2) * 64 + row] = k4.z;
            Kt[(f * 4 + 3) * 64 + row] = k4.w;
            float4 v4 = *(const float4*)(V + base + (size_t)(kv0 + row) * Dc + f * 4);
            *(float4*)(Vs + row * 128 + f * 4) = v4;
        }
        __syncthreads();

        // Scores: s[4q][4k] = Q . K^T  (reduce over d=128)
        float s[4][4];
#pragma unroll
        for (int i = 0; i < 4; ++i)
#pragma unroll
            for (int j = 0; j < 4; ++j) s[i][j] = 0.f;

#pragma unroll 8
        for (int d = 0; d < 128; ++d) {
            float4 a4 = *(const float4*)(Qt + d * 64 + ty * 4);
            float4 b4 = *(const float4*)(Kt + d * 64 + tx * 4);
            float a[4] = {a4.x, a4.y, a4.z, a4.w};
            float bb[4] = {b4.x, b4.y, b4.z, b4.w};
#pragma unroll
            for (int i = 0; i < 4; ++i)
#pragma unroll
                for (int j = 0; j < 4; ++j)
                    s[i][j] = fmaf(a[i], bb[j], s[i][j]);
        }

        // Online softmax (row = 16 tx-lanes within half-warp)
#pragma unroll
        for (int i = 0; i < 4; ++i) {
#pragma unroll
            for (int j = 0; j < 4; ++j) s[i][j] *= scale;
            float rm = fmaxf(fmaxf(s[i][0], s[i][1]), fmaxf(s[i][2], s[i][3]));
            rm = fmaxf(rm, __shfl_xor_sync(0xffffffffu, rm, 1));
            rm = fmaxf(rm, __shfl_xor_sync(0xffffffffu, rm, 2));
            rm = fmaxf(rm, __shfl_xor_sync(0xffffffffu, rm, 4));
            rm = fmaxf(rm, __shfl_xor_sync(0xffffffffu, rm, 8));
            const float mn   = fmaxf(m_i[i], rm);
            const float corr = __expf(m_i[i] - mn);
            float rs = 0.f;
#pragma unroll
            for (int j = 0; j < 4; ++j) {
                const float e = __expf(s[i][j] - mn);
                s[i][j] = e;
                rs += e;
            }
            rs += __shfl_xor_sync(0xffffffffu, rs, 1);
            rs += __shfl_xor_sync(0xffffffffu, rs, 2);
            rs += __shfl_xor_sync(0xffffffffu, rs, 4);
            rs += __shfl_xor_sync(0xffffffffu, rs, 8);
            l_i[i] = l_i[i] * corr + rs;
            m_i[i] = mn;
#pragma unroll
            for (int j = 0; j < 8; ++j) o[i][j] *= corr;
        }

        // Stage P (q-major) for the P@V GEMM
#pragma unroll
        for (int i = 0; i < 4; ++i) {
            float4 pv = make_float4(s[i][0], s[i][1], s[i][2], s[i][3]);
            *(float4*)(Ps + (ty * 4 + i) * PST + tx * 4) = pv;
        }
        __syncthreads();

        // O[4q][8d] += P @ V  (reduce over k=64)
#pragma unroll 4
        for (int kk = 0; kk < 64; ++kk) {
            float bb[8];
            *(float4*)(bb)     = *(const float4*)(Vs + kk * 128 + tx * 8);
            *(float4*)(bb + 4) = *(const float4*)(Vs + kk * 128 + tx * 8 + 4);
#pragma unroll
            for (int i = 0; i < 4; ++i) {
                const float a = Ps[(ty * 4 + i) * PST + kk];
#pragma unroll
                for (int j = 0; j < 8; ++j)
                    o[i][j] = fmaf(a, bb[j], o[i][j]);
            }
        }
    }

    // Epilogue: normalize and write [B,S,D] slice for this head
#pragma unroll
    for (int i = 0; i < 4; ++i) {
        const float inv = 1.f / l_i[i];
        const size_t off = base + (size_t)(q0 + ty * 4 + i) * Dc + tx * 8;
        float4 o0 = make_float4(o[i][0] * inv, o[i][1] * inv, o[i][2] * inv, o[i][3] * inv);
        float4 o1 = make_float4(o[i][4] * inv, o[i][5] * inv, o[i][6] * inv, o[i][7] * inv);
        *(float4*)(O + off)     = o0;
        *(float4*)(O + off + 4) = o1;
    }
}

// ---------------------------------------------------------------------------
// Inputs (metadata order): query, key, value, Wq, bq, Wk, bk, Wv, bv, Wo, bo
// ---------------------------------------------------------------------------
extern "C" void kernel_launch(void* const* d_in, const int* in_sizes, int n_in,
                              void* d_out, int out_size)
{
    const float* query = (const float*)d_in[0];
    const float* key   = (const float*)d_in[1];
    const float* value = (const float*)d_in[2];
    const float* Wq = (const float*)d_in[3];
    const float* bq = (const float*)d_in[4];
    const float* Wk = (const float*)d_in[5];
    const float* bk = (const float*)d_in[6];
    const float* Wv = (const float*)d_in[7];
    const float* bv = (const float*)d_in[8];
    const float* Wo = (const float*)d_in[9];
    const float* bo = (const float*)d_in[10];
    float* out = (float*)d_out;

    float *qb, *kb, *vb, *ab;
    cudaGetSymbolAddress((void**)&qb, g_q);
    cudaGetSymbolAddress((void**)&kb, g_k);
    cudaGetSymbolAddress((void**)&vb, g_v);
    cudaGetSymbolAddress((void**)&ab, g_att);

    const dim3 gblk(Dc / 128, Mc / 128);  // 16 x 64 blocks

    gemm_nt_bias<<<gblk, 256>>>(query, Wq, bq, qb, Mc, Dc, Dc);
    gemm_nt_bias<<<gblk, 256>>>(key,   Wk, bk, kb, Mc, Dc, Dc);
    gemm_nt_bias<<<gblk, 256>>>(value, Wv, bv, vb, Mc, Dc, Dc);

    cudaFuncSetAttribute(flash_kernel,
                         cudaFuncAttributeMaxDynamicSharedMemorySize, FLASH_SMEM);
    flash_kernel<<<dim3(Sc / 64, Hc, Bc), 256, FLASH_SMEM>>>(qb, kb, vb, ab);

    gemm_nt_bias<<<gblk, 256>>>(ab, Wo, bo, out, Mc, Dc, Dc);
}

// round 5
// speedup vs baseline: 1.5942x; 1.5942x over previous
#include <cuda_runtime.h>
#include <cuda_bf16.h>
#include <cstdint>
#include <math.h>

// Problem constants
#define Bc   4
#define Sc   2048
#define Dc   2048
#define Hc   16
#define DKc  128
#define Mc   (Bc * Sc)   // 8192 rows

// Scratch buffers (allocation-free rule: __device__ globals)
__device__ float g_q[(size_t)Mc * Dc];
__device__ float g_k[(size_t)Mc * Dc];
__device__ float g_v[(size_t)Mc * Dc];
__device__ float g_att[(size_t)Mc * Dc];

// ---------------------------------------------------------------------------
// Warp-level MMA helpers (stable PTX, works on plain sm_100 target)
// ---------------------------------------------------------------------------
__device__ __forceinline__ void ldmatrix_x4(uint32_t& r0, uint32_t& r1,
                                            uint32_t& r2, uint32_t& r3,
                                            uint32_t addr)
{
    asm volatile("ldmatrix.sync.aligned.m8n8.x4.shared.b16 {%0,%1,%2,%3}, [%4];"
                 : "=r"(r0), "=r"(r1), "=r"(r2), "=r"(r3) : "r"(addr));
}

__device__ __forceinline__ void mma_16816(float* c, const uint32_t* a,
                                          const uint32_t* b)
{
    asm volatile(
        "mma.sync.aligned.m16n8k16.row.col.f32.bf16.bf16.f32 "
        "{%0,%1,%2,%3}, {%4,%5,%6,%7}, {%8,%9}, {%0,%1,%2,%3};"
        : "+f"(c[0]), "+f"(c[1]), "+f"(c[2]), "+f"(c[3])
        : "r"(a[0]), "r"(a[1]), "r"(a[2]), "r"(a[3]), "r"(b[0]), "r"(b[1]));
}

__device__ __forceinline__ uint32_t smem_to_u32(const void* smem_ptr) {
    uint32_t addr;
    asm("{ .reg .u64 tmp; cvta.to.shared.u64 tmp, %1; cvt.u32.u64 %0, tmp; }"
        : "=r"(addr) : "l"(smem_ptr));
    return addr;
}

// ---------------------------------------------------------------------------
// fp32 -> bf16 big-little split (8 floats at a time)
// ---------------------------------------------------------------------------
__device__ __forceinline__ void cvt_split8(const float4& a, const float4& b,
                                           uint4& hi, uint4& lo)
{
    __nv_bfloat162 h0 = __float22bfloat162_rn(make_float2(a.x, a.y));
    __nv_bfloat162 h1 = __float22bfloat162_rn(make_float2(a.z, a.w));
    __nv_bfloat162 h2 = __float22bfloat162_rn(make_float2(b.x, b.y));
    __nv_bfloat162 h3 = __float22bfloat162_rn(make_float2(b.z, b.w));
    __nv_bfloat162 l0 = __float22bfloat162_rn(make_float2(a.x - __low2float(h0), a.y - __high2float(h0)));
    __nv_bfloat162 l1 = __float22bfloat162_rn(make_float2(a.z - __low2float(h1), a.w - __high2float(h1)));
    __nv_bfloat162 l2 = __float22bfloat162_rn(make_float2(b.x - __low2float(h2), b.y - __high2float(h2)));
    __nv_bfloat162 l3 = __float22bfloat162_rn(make_float2(b.z - __low2float(h3), b.w - __high2float(h3)));
    hi.x = *(uint32_t*)&h0; hi.y = *(uint32_t*)&h1;
    hi.z = *(uint32_t*)&h2; hi.w = *(uint32_t*)&h3;
    lo.x = *(uint32_t*)&l0; lo.y = *(uint32_t*)&l1;
    lo.z = *(uint32_t*)&l2; lo.w = *(uint32_t*)&l3;
}

// ---------------------------------------------------------------------------
// Tensor-core GEMM: C[M,N] = A[M,K] @ W[N,K]^T + bias[N], fp32 in/out.
// bf16 big-little split (hi*hi + hi*lo + lo*hi), mma.sync.m16n8k16.
// CTA tile 128x128, KC=64, 512 threads = 16 warps (4x4 grid, 32x32/warp).
// Smem: Ahi|Alo|Bhi|Blo, each 128 rows x 128B (SW128 swizzle), 64 KB.
// ---------------------------------------------------------------------------
#define KC      64
#define TILE_B  16384
#define GEMM_SMEM (4 * TILE_B)

__global__ __launch_bounds__(512, 1)
void gemm_tc(const float* __restrict__ A, const float* __restrict__ W,
             const float* __restrict__ bias, float* __restrict__ C,
             int M, int N, int K)
{
    extern __shared__ char smc[];
    const uint32_t sA_hi = smem_to_u32(smc);
    const uint32_t sA_lo = sA_hi + TILE_B;
    const uint32_t sB_hi = sA_hi + 2 * TILE_B;
    const uint32_t sB_lo = sA_hi + 3 * TILE_B;

    const int tid  = threadIdx.x;
    const int lane = tid & 31;
    const int wid  = tid >> 5;
    const int bm   = blockIdx.y * 128;
    const int bn   = blockIdx.x * 128;

    const int warpM = (wid & 3) * 32;   // warp row offset in tile
    const int warpN = (wid >> 2) * 32;  // warp col offset in tile

    // ldmatrix per-thread base addresses (byte offsets within a tile).
    // A (x4, covers m16 x k16): row = mbase + (lane&15), +16B if lane>=16.
    const int aRow  = warpM + (lane & 15);
    const uint32_t aXor = (uint32_t)(aRow & 7) << 4;
    const uint32_t aOffBase = (uint32_t)aRow * 128 + (((lane >> 4) & 1) << 4);
    // B (x4, covers n16 x k16): row = nbase + ((lane>>4)<<3) + (lane&7),
    //                           +16B if (lane>>3)&1.
    const int bRow  = warpN + ((lane >> 4) << 3) + (lane & 7);
    const uint32_t bXor = (uint32_t)(bRow & 7) << 4;
    const uint32_t bOffBase = (uint32_t)bRow * 128 + (((lane >> 3) & 1) << 4);

    // accumulators: 2 m16-tiles x 4 n8-tiles x 4 regs
    float acc[2][4][4];
#pragma unroll
    for (int i = 0; i < 2; ++i)
#pragma unroll
        for (int j = 0; j < 4; ++j)
#pragma unroll
            for (int r = 0; r < 4; ++r) acc[i][j][r] = 0.f;

    // loader tasks: id = tid + 512*j; id<1024 -> A, else B.
    // row = (id>>3)&127, kg = id&7 (8 fp32 = one 16B bf16 chunk after cvt).
    const int nchunk = K / KC;
    float4 pf[8];
    {
#pragma unroll
        for (int j = 0; j < 4; ++j) {
            int id  = tid + 512 * j;
            int row = (id >> 3) & 127;
            int kg  = id & 7;
            const float* p = (id < 1024)
                ? (A + (size_t)(bm + row) * K + kg * 8)
                : (W + (size_t)(bn + row) * K + kg * 8);
            pf[2 * j]     = *(const float4*)(p);
            pf[2 * j + 1] = *(const float4*)(p + 4);
        }
    }

    for (int c = 0; c < nchunk; ++c) {
        __syncthreads();   // all warps done reading smem from previous chunk

        // convert current chunk (in pf) to bf16 hi/lo and store to smem
#pragma unroll
        for (int j = 0; j < 4; ++j) {
            int id  = tid + 512 * j;
            int row = (id >> 3) & 127;
            int kg  = id & 7;
            uint32_t hiBase = (id < 1024) ? sA_hi : sB_hi;
            uint4 hi, lo;
            cvt_split8(pf[2 * j], pf[2 * j + 1], hi, lo);
            uint32_t off = (uint32_t)row * 128 + (uint32_t)kg * 16;
            uint32_t sw  = off ^ ((off >> 3) & 0x70);
            asm volatile("st.shared.v4.b32 [%0], {%1,%2,%3,%4};" ::
                         "r"(hiBase + sw), "r"(hi.x), "r"(hi.y), "r"(hi.z), "r"(hi.w));
            asm volatile("st.shared.v4.b32 [%0], {%1,%2,%3,%4};" ::
                         "r"(hiBase + TILE_B + sw), "r"(lo.x), "r"(lo.y), "r"(lo.z), "r"(lo.w));
        }

        // prefetch next chunk into pf (overlaps with MMA phase below)
        if (c + 1 < nchunk) {
            const int kc = (c + 1) * KC;
#pragma unroll
            for (int j = 0; j < 4; ++j) {
                int id  = tid + 512 * j;
                int row = (id >> 3) & 127;
                int kg  = id & 7;
                const float* p = (id < 1024)
                    ? (A + (size_t)(bm + row) * K + kc + kg * 8)
                    : (W + (size_t)(bn + row) * K + kc + kg * 8);
                pf[2 * j]     = *(const float4*)(p);
                pf[2 * j + 1] = *(const float4*)(p + 4);
            }
        }
        __syncthreads();   // smem tiles ready

        // MMA phase: 4 k16 steps, 3 passes each
#pragma unroll
        for (int ks = 0; ks < 4; ++ks) {
            const uint32_t kByte = (uint32_t)ks * 32;  // 16 bf16 = 32B
            uint32_t aH[2][4], aL[2][4], bH[2][4], bL[2][4];
#pragma unroll
            for (int mi = 0; mi < 2; ++mi) {
                uint32_t off = (aOffBase + (uint32_t)mi * 16 * 128 + kByte) ^ aXor;
                ldmatrix_x4(aH[mi][0], aH[mi][1], aH[mi][2], aH[mi][3], sA_hi + off);
                ldmatrix_x4(aL[mi][0], aL[mi][1], aL[mi][2], aL[mi][3], sA_lo + off);
            }
#pragma unroll
            for (int nj = 0; nj < 2; ++nj) {
                uint32_t off = (bOffBase + (uint32_t)nj * 16 * 128 + kByte) ^ bXor;
                ldmatrix_x4(bH[nj][0], bH[nj][1], bH[nj][2], bH[nj][3], sB_hi + off);
                ldmatrix_x4(bL[nj][0], bL[nj][1], bL[nj][2], bL[nj][3], sB_lo + off);
            }
#pragma unroll
            for (int mi = 0; mi < 2; ++mi) {
#pragma unroll
                for (int n8 = 0; n8 < 4; ++n8) {
                    const uint32_t* bh = &bH[n8 >> 1][(n8 & 1) * 2];
                    const uint32_t* bl = &bL[n8 >> 1][(n8 & 1) * 2];
                    mma_16816(acc[mi][n8], aH[mi], bh);
                    mma_16816(acc[mi][n8], aH[mi], bl);
                    mma_16816(acc[mi][n8], aL[mi], bh);
                }
            }
        }
    }

    // Epilogue: c-frag (m16n8): r0,r1 -> (row, col..col+1); r2,r3 -> (row+8, ...)
    const int rBase = bm + warpM + (lane >> 2);
    const int cBase = bn + warpN + (lane & 3) * 2;
#pragma unroll
    for (int mi = 0; mi < 2; ++mi) {
#pragma unroll
        for (int n8 = 0; n8 < 4; ++n8) {
            const int row = rBase + mi * 16;
            const int col = cBase + n8 * 8;
            const float b0 = __ldg(&bias[col]);
            const float b1 = __ldg(&bias[col + 1]);
            float2 v0 = make_float2(acc[mi][n8][0] + b0, acc[mi][n8][1] + b1);
            float2 v1 = make_float2(acc[mi][n8][2] + b0, acc[mi][n8][3] + b1);
            *(float2*)(&C[(size_t)row * N + col])       = v0;
            *(float2*)(&C[(size_t)(row + 8) * N + col]) = v1;
        }
    }
}

// ---------------------------------------------------------------------------
// Flash attention, fp32 (unchanged from R1 — passed at 4.5 ms)
// ---------------------------------------------------------------------------
#define PST 68
#define FLASH_SMEM ((3 * 128 * 64 + 64 * PST) * (int)sizeof(float))

__global__ __launch_bounds__(256, 1)
void flash_kernel(const float* __restrict__ Q, const float* __restrict__ K,
                  const float* __restrict__ V, float* __restrict__ O)
{
    extern __shared__ float smf[];
    float* Qt = smf;
    float* Kt = smf + 128 * 64;
    float* Vs = smf + 2 * 128 * 64;
    float* Ps = smf + 3 * 128 * 64;

    const int tid = threadIdx.x;
    const int tx  = tid & 15;
    const int ty  = tid >> 4;
    const int q0  = blockIdx.x * 64;
    const int h   = blockIdx.y;
    const int b   = blockIdx.z;
    const size_t base = (size_t)b * Sc * Dc + (size_t)h * DKc;
    const float scale = 0.08838834764831845f;

    const int f  = tid & 31;
    const int r0 = (tid >> 5) * 8;

#pragma unroll
    for (int rr = 0; rr < 8; ++rr) {
        const int row = r0 + rr;
        float4 q4 = *(const float4*)(Q + base + (size_t)(q0 + row) * Dc + f * 4);
        Qt[(f * 4 + 0) * 64 + row] = q4.x;
        Qt[(f * 4 + 1) * 64 + row] = q4.y;
        Qt[(f * 4 + 2) * 64 + row] = q4.z;
        Qt[(f * 4 + 3) * 64 + row] = q4.w;
    }

    float m_i[4], l_i[4], o[4][8];
#pragma unroll
    for (int i = 0; i < 4; ++i) {
        m_i[i] = -1e30f;
        l_i[i] = 0.f;
#pragma unroll
        for (int j = 0; j < 8; ++j) o[i][j] = 0.f;
    }

    for (int kv0 = 0; kv0 < Sc; kv0 += 64) {
        __syncthreads();
#pragma unroll
        for (int rr = 0; rr < 8; ++rr) {
            const int row = r0 + rr;
            float4 k4 = *(const float4*)(K + base + (size_t)(kv0 + row) * Dc + f * 4);
            Kt[(f * 4 + 0) * 64 + row] = k4.x;
            Kt[(f * 4 + 1) * 64 + row] = k4.y;
            Kt[(f * 4 + 2) * 64 + row] = k4.z;
            Kt[(f * 4 + 3) * 64 + row] = k4.w;
            float4 v4 = *(const float4*)(V + base + (size_t)(kv0 + row) * Dc + f * 4);
            *(float4*)(Vs + row * 128 + f * 4) = v4;
        }
        __syncthreads();

        float s[4][4];
#pragma unroll
        for (int i = 0; i < 4; ++i)
#pragma unroll
            for (int j = 0; j < 4; ++j) s[i][j] = 0.f;

#pragma unroll 8
        for (int d = 0; d < 128; ++d) {
            float4 a4 = *(const float4*)(Qt + d * 64 + ty * 4);
            float4 b4 = *(const float4*)(Kt + d * 64 + tx * 4);
            float a[4] = {a4.x, a4.y, a4.z, a4.w};
            float bb[4] = {b4.x, b4.y, b4.z, b4.w};
#pragma unroll
            for (int i = 0; i < 4; ++i)
#pragma unroll
                for (int j = 0; j < 4; ++j)
                    s[i][j] = fmaf(a[i], bb[j], s[i][j]);
        }

#pragma unroll
        for (int i = 0; i < 4; ++i) {
#pragma unroll
            for (int j = 0; j < 4; ++j) s[i][j] *= scale;
            float rm = fmaxf(fmaxf(s[i][0], s[i][1]), fmaxf(s[i][2], s[i][3]));
            rm = fmaxf(rm, __shfl_xor_sync(0xffffffffu, rm, 1));
            rm = fmaxf(rm, __shfl_xor_sync(0xffffffffu, rm, 2));
            rm = fmaxf(rm, __shfl_xor_sync(0xffffffffu, rm, 4));
            rm = fmaxf(rm, __shfl_xor_sync(0xffffffffu, rm, 8));
            const float mn   = fmaxf(m_i[i], rm);
            const float corr = __expf(m_i[i] - mn);
            float rs = 0.f;
#pragma unroll
            for (int j = 0; j < 4; ++j) {
                const float e = __expf(s[i][j] - mn);
                s[i][j] = e;
                rs += e;
            }
            rs += __shfl_xor_sync(0xffffffffu, rs, 1);
            rs += __shfl_xor_sync(0xffffffffu, rs, 2);
            rs += __shfl_xor_sync(0xffffffffu, rs, 4);
            rs += __shfl_xor_sync(0xffffffffu, rs, 8);
            l_i[i] = l_i[i] * corr + rs;
            m_i[i] = mn;
#pragma unroll
            for (int j = 0; j < 8; ++j) o[i][j] *= corr;
        }

#pragma unroll
        for (int i = 0; i < 4; ++i) {
            float4 pv = make_float4(s[i][0], s[i][1], s[i][2], s[i][3]);
            *(float4*)(Ps + (ty * 4 + i) * PST + tx * 4) = pv;
        }
        __syncthreads();

#pragma unroll 4
        for (int kk = 0; kk < 64; ++kk) {
            float bb[8];
            *(float4*)(bb)     = *(const float4*)(Vs + kk * 128 + tx * 8);
            *(float4*)(bb + 4) = *(const float4*)(Vs + kk * 128 + tx * 8 + 4);
#pragma unroll
            for (int i = 0; i < 4; ++i) {
                const float a = Ps[(ty * 4 + i) * PST + kk];
#pragma unroll
                for (int j = 0; j < 8; ++j)
                    o[i][j] = fmaf(a, bb[j], o[i][j]);
            }
        }
    }

#pragma unroll
    for (int i = 0; i < 4; ++i) {
        const float inv = 1.f / l_i[i];
        const size_t off = base + (size_t)(q0 + ty * 4 + i) * Dc + tx * 8;
        float4 o0 = make_float4(o[i][0] * inv, o[i][1] * inv, o[i][2] * inv, o[i][3] * inv);
        float4 o1 = make_float4(o[i][4] * inv, o[i][5] * inv, o[i][6] * inv, o[i][7] * inv);
        *(float4*)(O + off)     = o0;
        *(float4*)(O + off + 4) = o1;
    }
}

// ---------------------------------------------------------------------------
// Inputs: query, key, value, Wq, bq, Wk, bk, Wv, bv, Wo, bo
// ---------------------------------------------------------------------------
extern "C" void kernel_launch(void* const* d_in, const int* in_sizes, int n_in,
                              void* d_out, int out_size)
{
    const float* query = (const float*)d_in[0];
    const float* key   = (const float*)d_in[1];
    const float* value = (const float*)d_in[2];
    const float* Wq = (const float*)d_in[3];
    const float* bq = (const float*)d_in[4];
    const float* Wk = (const float*)d_in[5];
    const float* bk = (const float*)d_in[6];
    const float* Wv = (const float*)d_in[7];
    const float* bv = (const float*)d_in[8];
    const float* Wo = (const float*)d_in[9];
    const float* bo = (const float*)d_in[10];
    float* out = (float*)d_out;

    float *qb, *kb, *vb, *ab;
    cudaGetSymbolAddress((void**)&qb, g_q);
    cudaGetSymbolAddress((void**)&kb, g_k);
    cudaGetSymbolAddress((void**)&vb, g_v);
    cudaGetSymbolAddress((void**)&ab, g_att);

    cudaFuncSetAttribute(gemm_tc,
                         cudaFuncAttributeMaxDynamicSharedMemorySize, GEMM_SMEM);
    cudaFuncSetAttribute(flash_kernel,
                         cudaFuncAttributeMaxDynamicSharedMemorySize, FLASH_SMEM);

    const dim3 gblk(Dc / 128, Mc / 128);  // 16 x 64

    gemm_tc<<<gblk, 512, GEMM_SMEM>>>(query, Wq, bq, qb, Mc, Dc, Dc);
    gemm_tc<<<gblk, 512, GEMM_SMEM>>>(key,   Wk, bk, kb, Mc, Dc, Dc);
    gemm_tc<<<gblk, 512, GEMM_SMEM>>>(value, Wv, bv, vb, Mc, Dc, Dc);

    flash_kernel<<<dim3(Sc / 64, Hc, Bc), 256, FLASH_SMEM>>>(qb, kb, vb, ab);

    gemm_tc<<<gblk, 512, GEMM_SMEM>>>(ab, Wo, bo, out, Mc, Dc, Dc);
}

// round 6
// speedup vs baseline: 2.9984x; 1.8808x over previous
#include <cuda_runtime.h>
#include <cuda_bf16.h>
#include <cstdint>
#include <math.h>

// Problem constants
#define Bc   4
#define Sc   2048
#define Dc   2048
#define Hc   16
#define DKc  128
#define Mc   (Bc * Sc)   // 8192 rows

// Scratch buffers (allocation-free rule: __device__ globals)
__device__ float g_q[(size_t)Mc * Dc];
__device__ float g_k[(size_t)Mc * Dc];
__device__ float g_v[(size_t)Mc * Dc];
__device__ float g_att[(size_t)Mc * Dc];

// ---------------------------------------------------------------------------
// Warp-level MMA helpers (stable PTX, works on plain sm_100 target)
// ---------------------------------------------------------------------------
__device__ __forceinline__ void ldmatrix_x4(uint32_t& r0, uint32_t& r1,
                                            uint32_t& r2, uint32_t& r3,
                                            uint32_t addr)
{
    asm volatile("ldmatrix.sync.aligned.m8n8.x4.shared.b16 {%0,%1,%2,%3}, [%4];"
                 : "=r"(r0), "=r"(r1), "=r"(r2), "=r"(r3) : "r"(addr));
}

__device__ __forceinline__ void ldmatrix_x4_trans(uint32_t& r0, uint32_t& r1,
                                                  uint32_t& r2, uint32_t& r3,
                                                  uint32_t addr)
{
    asm volatile("ldmatrix.sync.aligned.m8n8.x4.trans.shared.b16 {%0,%1,%2,%3}, [%4];"
                 : "=r"(r0), "=r"(r1), "=r"(r2), "=r"(r3) : "r"(addr));
}

__device__ __forceinline__ void mma_16816(float* c, const uint32_t* a,
                                          const uint32_t* b)
{
    asm volatile(
        "mma.sync.aligned.m16n8k16.row.col.f32.bf16.bf16.f32 "
        "{%0,%1,%2,%3}, {%4,%5,%6,%7}, {%8,%9}, {%0,%1,%2,%3};"
        : "+f"(c[0]), "+f"(c[1]), "+f"(c[2]), "+f"(c[3])
        : "r"(a[0]), "r"(a[1]), "r"(a[2]), "r"(a[3]), "r"(b[0]), "r"(b[1]));
}

__device__ __forceinline__ uint32_t smem_to_u32(const void* smem_ptr) {
    uint32_t addr;
    asm("{ .reg .u64 tmp; cvta.to.shared.u64 tmp, %1; cvt.u32.u64 %0, tmp; }"
        : "=r"(addr) : "l"(smem_ptr));
    return addr;
}

// ---------------------------------------------------------------------------
// fp32 -> bf16 big-little split (8 floats at a time)
// ---------------------------------------------------------------------------
__device__ __forceinline__ void cvt_split8(const float4& a, const float4& b,
                                           uint4& hi, uint4& lo)
{
    __nv_bfloat162 h0 = __float22bfloat162_rn(make_float2(a.x, a.y));
    __nv_bfloat162 h1 = __float22bfloat162_rn(make_float2(a.z, a.w));
    __nv_bfloat162 h2 = __float22bfloat162_rn(make_float2(b.x, b.y));
    __nv_bfloat162 h3 = __float22bfloat162_rn(make_float2(b.z, b.w));
    __nv_bfloat162 l0 = __float22bfloat162_rn(make_float2(a.x - __low2float(h0), a.y - __high2float(h0)));
    __nv_bfloat162 l1 = __float22bfloat162_rn(make_float2(a.z - __low2float(h1), a.w - __high2float(h1)));
    __nv_bfloat162 l2 = __float22bfloat162_rn(make_float2(b.x - __low2float(h2), b.y - __high2float(h2)));
    __nv_bfloat162 l3 = __float22bfloat162_rn(make_float2(b.z - __low2float(h3), b.w - __high2float(h3)));
    hi.x = *(uint32_t*)&h0; hi.y = *(uint32_t*)&h1;
    hi.z = *(uint32_t*)&h2; hi.w = *(uint32_t*)&h3;
    lo.x = *(uint32_t*)&l0; lo.y = *(uint32_t*)&l1;
    lo.z = *(uint32_t*)&l2; lo.w = *(uint32_t*)&l3;
}

// ---------------------------------------------------------------------------
// Tensor-core GEMM (unchanged from R5 — passed, rel_err 2.9e-5)
// ---------------------------------------------------------------------------
#define KC      64
#define TILE_B  16384
#define GEMM_SMEM (4 * TILE_B)

__global__ __launch_bounds__(512, 1)
void gemm_tc(const float* __restrict__ A, const float* __restrict__ W,
             const float* __restrict__ bias, float* __restrict__ C,
             int M, int N, int K)
{
    extern __shared__ char smc[];
    const uint32_t sA_hi = smem_to_u32(smc);
    const uint32_t sA_lo = sA_hi + TILE_B;
    const uint32_t sB_hi = sA_hi + 2 * TILE_B;
    const uint32_t sB_lo = sA_hi + 3 * TILE_B;

    const int tid  = threadIdx.x;
    const int lane = tid & 31;
    const int wid  = tid >> 5;
    const int bm   = blockIdx.y * 128;
    const int bn   = blockIdx.x * 128;

    const int warpM = (wid & 3) * 32;
    const int warpN = (wid >> 2) * 32;

    const int aRow  = warpM + (lane & 15);
    const uint32_t aXor = (uint32_t)(aRow & 7) << 4;
    const uint32_t aOffBase = (uint32_t)aRow * 128 + (((lane >> 4) & 1) << 4);
    const int bRow  = warpN + ((lane >> 4) << 3) + (lane & 7);
    const uint32_t bXor = (uint32_t)(bRow & 7) << 4;
    const uint32_t bOffBase = (uint32_t)bRow * 128 + (((lane >> 3) & 1) << 4);

    float acc[2][4][4];
#pragma unroll
    for (int i = 0; i < 2; ++i)
#pragma unroll
        for (int j = 0; j < 4; ++j)
#pragma unroll
            for (int r = 0; r < 4; ++r) acc[i][j][r] = 0.f;

    const int nchunk = K / KC;
    float4 pf[8];
    {
#pragma unroll
        for (int j = 0; j < 4; ++j) {
            int id  = tid + 512 * j;
            int row = (id >> 3) & 127;
            int kg  = id & 7;
            const float* p = (id < 1024)
                ? (A + (size_t)(bm + row) * K + kg * 8)
                : (W + (size_t)(bn + row) * K + kg * 8);
            pf[2 * j]     = *(const float4*)(p);
            pf[2 * j + 1] = *(const float4*)(p + 4);
        }
    }

    for (int c = 0; c < nchunk; ++c) {
        __syncthreads();
#pragma unroll
        for (int j = 0; j < 4; ++j) {
            int id  = tid + 512 * j;
            int row = (id >> 3) & 127;
            int kg  = id & 7;
            uint32_t hiBase = (id < 1024) ? sA_hi : sB_hi;
            uint4 hi, lo;
            cvt_split8(pf[2 * j], pf[2 * j + 1], hi, lo);
            uint32_t off = (uint32_t)row * 128 + (uint32_t)kg * 16;
            uint32_t sw  = off ^ ((off >> 3) & 0x70);
            asm volatile("st.shared.v4.b32 [%0], {%1,%2,%3,%4};" ::
                         "r"(hiBase + sw), "r"(hi.x), "r"(hi.y), "r"(hi.z), "r"(hi.w));
            asm volatile("st.shared.v4.b32 [%0], {%1,%2,%3,%4};" ::
                         "r"(hiBase + TILE_B + sw), "r"(lo.x), "r"(lo.y), "r"(lo.z), "r"(lo.w));
        }

        if (c + 1 < nchunk) {
            const int kc = (c + 1) * KC;
#pragma unroll
            for (int j = 0; j < 4; ++j) {
                int id  = tid + 512 * j;
                int row = (id >> 3) & 127;
                int kg  = id & 7;
                const float* p = (id < 1024)
                    ? (A + (size_t)(bm + row) * K + kc + kg * 8)
                    : (W + (size_t)(bn + row) * K + kc + kg * 8);
                pf[2 * j]     = *(const float4*)(p);
                pf[2 * j + 1] = *(const float4*)(p + 4);
            }
        }
        __syncthreads();

#pragma unroll
        for (int ks = 0; ks < 4; ++ks) {
            const uint32_t kByte = (uint32_t)ks * 32;
            uint32_t aH[2][4], aL[2][4], bH[2][4], bL[2][4];
#pragma unroll
            for (int mi = 0; mi < 2; ++mi) {
                uint32_t off = (aOffBase + (uint32_t)mi * 16 * 128 + kByte) ^ aXor;
                ldmatrix_x4(aH[mi][0], aH[mi][1], aH[mi][2], aH[mi][3], sA_hi + off);
                ldmatrix_x4(aL[mi][0], aL[mi][1], aL[mi][2], aL[mi][3], sA_lo + off);
            }
#pragma unroll
            for (int nj = 0; nj < 2; ++nj) {
                uint32_t off = (bOffBase + (uint32_t)nj * 16 * 128 + kByte) ^ bXor;
                ldmatrix_x4(bH[nj][0], bH[nj][1], bH[nj][2], bH[nj][3], sB_hi + off);
                ldmatrix_x4(bL[nj][0], bL[nj][1], bL[nj][2], bL[nj][3], sB_lo + off);
            }
#pragma unroll
            for (int mi = 0; mi < 2; ++mi) {
#pragma unroll
                for (int n8 = 0; n8 < 4; ++n8) {
                    const uint32_t* bh = &bH[n8 >> 1][(n8 & 1) * 2];
                    const uint32_t* bl = &bL[n8 >> 1][(n8 & 1) * 2];
                    mma_16816(acc[mi][n8], aH[mi], bh);
                    mma_16816(acc[mi][n8], aH[mi], bl);
                    mma_16816(acc[mi][n8], aL[mi], bh);
                }
            }
        }
    }

    const int rBase = bm + warpM + (lane >> 2);
    const int cBase = bn + warpN + (lane & 3) * 2;
#pragma unroll
    for (int mi = 0; mi < 2; ++mi) {
#pragma unroll
        for (int n8 = 0; n8 < 4; ++n8) {
            const int row = rBase + mi * 16;
            const int col = cBase + n8 * 8;
            const float b0 = __ldg(&bias[col]);
            const float b1 = __ldg(&bias[col + 1]);
            float2 v0 = make_float2(acc[mi][n8][0] + b0, acc[mi][n8][1] + b1);
            float2 v1 = make_float2(acc[mi][n8][2] + b0, acc[mi][n8][3] + b1);
            *(float2*)(&C[(size_t)row * N + col])       = v0;
            *(float2*)(&C[(size_t)(row + 8) * N + col]) = v1;
        }
    }
}

// ---------------------------------------------------------------------------
// Tensor-core flash attention. BQ=128, BKV=64, DK=128.
// 256 threads = 8 warps; warp w owns q rows 16w..16w+15 (one m16 tile).
// All operands bf16 big-little split (3-pass MMA). Softmax in C-fragments;
// P re-packed C-frag -> A-frag; V via ldmatrix.trans.
// Smem (bf16, 64-col subtiles of 128B rows, SW128 swizzle):
//   Qhi 32K | Qlo 32K | Khi 16K | Klo 16K | Vhi 16K | Vlo 16K = 128 KB
// ---------------------------------------------------------------------------
#define FQ_HI   0
#define FQ_LO   32768
#define FK_HI   65536
#define FK_LO   81920
#define FV_HI   98304
#define FV_LO   114688
#define FLASH_SMEM 131072
// Q subtile = 128 rows * 128B = 16384; K/V subtile = 64 rows * 128B = 8192.

__global__ __launch_bounds__(256, 1)
void flash_tc(const float* __restrict__ Q, const float* __restrict__ K,
              const float* __restrict__ V, float* __restrict__ O)
{
    extern __shared__ char smf[];
    const uint32_t sb = smem_to_u32(smf);

    const int tid  = threadIdx.x;
    const int lane = tid & 31;
    const int wid  = tid >> 5;
    const int q0   = blockIdx.x * 128;
    const int h    = blockIdx.y;
    const int b    = blockIdx.z;
    const size_t base = (size_t)b * Sc * Dc + (size_t)h * DKc;

    // scale folded into Q: 1/sqrt(128) * log2(e)  (softmax done in base 2)
    const float qscale = 0.08838834764831845f * 1.4426950408889634f;

    // ---- Load Q tile (128 x 128), scale, split, store swizzled -------------
    {
#pragma unroll
        for (int t = 0; t < 8; ++t) {
            int id  = tid + 256 * t;        // 0..2047
            int row = id >> 4;              // 0..127
            int kg  = id & 15;              // 8-float group
            const float* p = Q + base + (size_t)(q0 + row) * Dc + kg * 8;
            float4 v0 = *(const float4*)(p);
            float4 v1 = *(const float4*)(p + 4);
            v0.x *= qscale; v0.y *= qscale; v0.z *= qscale; v0.w *= qscale;
            v1.x *= qscale; v1.y *= qscale; v1.z *= qscale; v1.w *= qscale;
            uint4 hi, lo;
            cvt_split8(v0, v1, hi, lo);
            uint32_t sub = (kg >> 3) * 16384;
            uint32_t off = (uint32_t)row * 128 + (uint32_t)(kg & 7) * 16;
            uint32_t sw  = off ^ ((off >> 3) & 0x70);
            asm volatile("st.shared.v4.b32 [%0], {%1,%2,%3,%4};" ::
                         "r"(sb + FQ_HI + sub + sw), "r"(hi.x), "r"(hi.y), "r"(hi.z), "r"(hi.w));
            asm volatile("st.shared.v4.b32 [%0], {%1,%2,%3,%4};" ::
                         "r"(sb + FQ_LO + sub + sw), "r"(lo.x), "r"(lo.y), "r"(lo.z), "r"(lo.w));
        }
    }

    // ---- fragment addressing ------------------------------------------------
    // A-frag (Q): warp's m16 tile
    const int aRow = wid * 16 + (lane & 15);
    const uint32_t aXor = (uint32_t)(aRow & 7) << 4;
    const uint32_t aOff = (uint32_t)aRow * 128 + (((lane >> 4) & 1) << 4);
    // B-frag (K): n16 groups
    const int bRowL = ((lane >> 4) << 3) + (lane & 7);
    const uint32_t bXor = (uint32_t)(bRowL & 7) << 4;
    const uint32_t bOff = (uint32_t)bRowL * 128 + (((lane >> 3) & 1) << 4);
    // B-frag (V, trans): k rows
    const uint32_t vXor = (uint32_t)(lane & 7) << 4;
    const uint32_t vOff = (uint32_t)(lane & 15) * 128 + (((lane >> 4) & 1) << 4);

    // ---- state --------------------------------------------------------------
    float o[16][4];
#pragma unroll
    for (int d = 0; d < 16; ++d)
#pragma unroll
        for (int r = 0; r < 4; ++r) o[d][r] = 0.f;
    float m0 = -1e30f, m1 = -1e30f, l0 = 0.f, l1 = 0.f;

    for (int kv0 = 0; kv0 < Sc; kv0 += 64) {
        __syncthreads();   // previous K/V consumption done
        // ---- load K/V tile (64 x 128 each), split, store --------------------
#pragma unroll
        for (int t = 0; t < 4; ++t) {
            int id  = tid + 256 * t;        // 0..1023
            int row = id >> 4;              // 0..63
            int kg  = id & 15;
            uint32_t sub = (kg >> 3) * 8192;
            uint32_t off = (uint32_t)row * 128 + (uint32_t)(kg & 7) * 16;
            uint32_t sw  = (off ^ ((off >> 3) & 0x70)) + sub;
            {
                const float* p = K + base + (size_t)(kv0 + row) * Dc + kg * 8;
                uint4 hi, lo;
                cvt_split8(*(const float4*)(p), *(const float4*)(p + 4), hi, lo);
                asm volatile("st.shared.v4.b32 [%0], {%1,%2,%3,%4};" ::
                             "r"(sb + FK_HI + sw), "r"(hi.x), "r"(hi.y), "r"(hi.z), "r"(hi.w));
                asm volatile("st.shared.v4.b32 [%0], {%1,%2,%3,%4};" ::
                             "r"(sb + FK_LO + sw), "r"(lo.x), "r"(lo.y), "r"(lo.z), "r"(lo.w));
            }
            {
                const float* p = V + base + (size_t)(kv0 + row) * Dc + kg * 8;
                uint4 hi, lo;
                cvt_split8(*(const float4*)(p), *(const float4*)(p + 4), hi, lo);
                asm volatile("st.shared.v4.b32 [%0], {%1,%2,%3,%4};" ::
                             "r"(sb + FV_HI + sw), "r"(hi.x), "r"(hi.y), "r"(hi.z), "r"(hi.w));
                asm volatile("st.shared.v4.b32 [%0], {%1,%2,%3,%4};" ::
                             "r"(sb + FV_LO + sw), "r"(lo.x), "r"(lo.y), "r"(lo.z), "r"(lo.w));
            }
        }
        __syncthreads();

        // ---- scores: S[16, 64] = Q . K^T (3-pass split) ---------------------
        float s[8][4];
#pragma unroll
        for (int t = 0; t < 8; ++t)
#pragma unroll
            for (int r = 0; r < 4; ++r) s[t][r] = 0.f;

#pragma unroll
        for (int ks = 0; ks < 8; ++ks) {
            uint32_t aoff = ((uint32_t)(ks >> 2)) * 16384 + ((aOff + (uint32_t)(ks & 3) * 32) ^ aXor);
            uint32_t aH[4], aL[4];
            ldmatrix_x4(aH[0], aH[1], aH[2], aH[3], sb + FQ_HI + aoff);
            ldmatrix_x4(aL[0], aL[1], aL[2], aL[3], sb + FQ_LO + aoff);
#pragma unroll
            for (int nj = 0; nj < 4; ++nj) {
                uint32_t koff = ((uint32_t)(ks >> 2)) * 8192 +
                    ((bOff + (uint32_t)nj * 2048 + (uint32_t)(ks & 3) * 32) ^ bXor);
                uint32_t bH[4], bL[4];
                ldmatrix_x4(bH[0], bH[1], bH[2], bH[3], sb + FK_HI + koff);
                ldmatrix_x4(bL[0], bL[1], bL[2], bL[3], sb + FK_LO + koff);
                mma_16816(s[2 * nj],     aH, bH);
                mma_16816(s[2 * nj],     aH, bL);
                mma_16816(s[2 * nj],     aL, bH);
                mma_16816(s[2 * nj + 1], aH, bH + 2);
                mma_16816(s[2 * nj + 1], aH, bL + 2);
                mma_16816(s[2 * nj + 1], aL, bH + 2);
            }
        }

        // ---- online softmax (base-2; rows r1 = lane>>2, r2 = r1+8) ----------
        float rm0 = -1e30f, rm1 = -1e30f;
#pragma unroll
        for (int t = 0; t < 8; ++t) {
            rm0 = fmaxf(rm0, fmaxf(s[t][0], s[t][1]));
            rm1 = fmaxf(rm1, fmaxf(s[t][2], s[t][3]));
        }
        rm0 = fmaxf(rm0, __shfl_xor_sync(0xffffffffu, rm0, 1));
        rm0 = fmaxf(rm0, __shfl_xor_sync(0xffffffffu, rm0, 2));
        rm1 = fmaxf(rm1, __shfl_xor_sync(0xffffffffu, rm1, 1));
        rm1 = fmaxf(rm1, __shfl_xor_sync(0xffffffffu, rm1, 2));

        const float mn0 = fmaxf(m0, rm0);
        const float mn1 = fmaxf(m1, rm1);
        const float c0  = exp2f(m0 - mn0);
        const float c1  = exp2f(m1 - mn1);

        float rs0 = 0.f, rs1 = 0.f;
#pragma unroll
        for (int t = 0; t < 8; ++t) {
            s[t][0] = exp2f(s[t][0] - mn0);
            s[t][1] = exp2f(s[t][1] - mn0);
            s[t][2] = exp2f(s[t][2] - mn1);
            s[t][3] = exp2f(s[t][3] - mn1);
            rs0 += s[t][0] + s[t][1];
            rs1 += s[t][2] + s[t][3];
        }
        rs0 += __shfl_xor_sync(0xffffffffu, rs0, 1);
        rs0 += __shfl_xor_sync(0xffffffffu, rs0, 2);
        rs1 += __shfl_xor_sync(0xffffffffu, rs1, 1);
        rs1 += __shfl_xor_sync(0xffffffffu, rs1, 2);

        l0 = l0 * c0 + rs0;
        l1 = l1 * c1 + rs1;
        m0 = mn0;
        m1 = mn1;
#pragma unroll
        for (int d = 0; d < 16; ++d) {
            o[d][0] *= c0; o[d][1] *= c0;
            o[d][2] *= c1; o[d][3] *= c1;
        }

        // ---- PV: O[16, 128] += P . V (3-pass split) -------------------------
#pragma unroll
        for (int j = 0; j < 4; ++j) {
            // pack P C-frags (tiles 2j, 2j+1) into A-frags, hi + lo
            uint32_t aPh[4], aPl[4];
#pragma unroll
            for (int hh = 0; hh < 2; ++hh) {
                const float* st = s[2 * j + hh];
                __nv_bfloat162 h01 = __float22bfloat162_rn(make_float2(st[0], st[1]));
                __nv_bfloat162 h23 = __float22bfloat162_rn(make_float2(st[2], st[3]));
                __nv_bfloat162 l01 = __float22bfloat162_rn(make_float2(
                    st[0] - __low2float(h01), st[1] - __high2float(h01)));
                __nv_bfloat162 l23 = __float22bfloat162_rn(make_float2(
                    st[2] - __low2float(h23), st[3] - __high2float(h23)));
                aPh[2 * hh]     = *(uint32_t*)&h01;   // a0/a2: row r1
                aPh[2 * hh + 1] = *(uint32_t*)&h23;   // a1/a3: row r2
                aPl[2 * hh]     = *(uint32_t*)&l01;
                aPl[2 * hh + 1] = *(uint32_t*)&l23;
            }
#pragma unroll
            for (int sub = 0; sub < 2; ++sub) {
#pragma unroll
                for (int dt4 = 0; dt4 < 4; ++dt4) {
                    uint32_t voff = (uint32_t)sub * 8192 +
                        ((vOff + (uint32_t)j * 2048 + (uint32_t)dt4 * 32) ^ vXor);
                    uint32_t bVh[4], bVl[4];
                    ldmatrix_x4_trans(bVh[0], bVh[1], bVh[2], bVh[3], sb + FV_HI + voff);
                    ldmatrix_x4_trans(bVl[0], bVl[1], bVl[2], bVl[3], sb + FV_LO + voff);
                    const int dt = sub * 8 + dt4 * 2;
                    mma_16816(o[dt],     aPh, bVh);
                    mma_16816(o[dt],     aPh, bVl);
                    mma_16816(o[dt],     aPl, bVh);
                    mma_16816(o[dt + 1], aPh, bVh + 2);
                    mma_16816(o[dt + 1], aPh, bVl + 2);
                    mma_16816(o[dt + 1], aPl, bVh + 2);
                }
            }
        }
    }

    // ---- epilogue: normalize, write [B,S,D] head slice ----------------------
    const float inv0 = 1.f / l0;
    const float inv1 = 1.f / l1;
    const int row1 = q0 + wid * 16 + (lane >> 2);
    const int row2 = row1 + 8;
#pragma unroll
    for (int dt = 0; dt < 16; ++dt) {
        const int d = dt * 8 + (lane & 3) * 2;
        float2 v0 = make_float2(o[dt][0] * inv0, o[dt][1] * inv0);
        float2 v1 = make_float2(o[dt][2] * inv1, o[dt][3] * inv1);
        *(float2*)(O + base + (size_t)row1 * Dc + d) = v0;
        *(float2*)(O + base + (size_t)row2 * Dc + d) = v1;
    }
}

// ---------------------------------------------------------------------------
// Inputs: query, key, value, Wq, bq, Wk, bk, Wv, bv, Wo, bo
// ---------------------------------------------------------------------------
extern "C" void kernel_launch(void* const* d_in, const int* in_sizes, int n_in,
                              void* d_out, int out_size)
{
    const float* query = (const float*)d_in[0];
    const float* key   = (const float*)d_in[1];
    const float* value = (const float*)d_in[2];
    const float* Wq = (const float*)d_in[3];
    const float* bq = (const float*)d_in[4];
    const float* Wk = (const float*)d_in[5];
    const float* bk = (const float*)d_in[6];
    const float* Wv = (const float*)d_in[7];
    const float* bv = (const float*)d_in[8];
    const float* Wo = (const float*)d_in[9];
    const float* bo = (const float*)d_in[10];
    float* out = (float*)d_out;

    float *qb, *kb, *vb, *ab;
    cudaGetSymbolAddress((void**)&qb, g_q);
    cudaGetSymbolAddress((void**)&kb, g_k);
    cudaGetSymbolAddress((void**)&vb, g_v);
    cudaGetSymbolAddress((void**)&ab, g_att);

    cudaFuncSetAttribute(gemm_tc,
                         cudaFuncAttributeMaxDynamicSharedMemorySize, GEMM_SMEM);
    cudaFuncSetAttribute(flash_tc,
                         cudaFuncAttributeMaxDynamicSharedMemorySize, FLASH_SMEM);

    const dim3 gblk(Dc / 128, Mc / 128);  // 16 x 64

    gemm_tc<<<gblk, 512, GEMM_SMEM>>>(query, Wq, bq, qb, Mc, Dc, Dc);
    gemm_tc<<<gblk, 512, GEMM_SMEM>>>(key,   Wk, bk, kb, Mc, Dc, Dc);
    gemm_tc<<<gblk, 512, GEMM_SMEM>>>(value, Wv, bv, vb, Mc, Dc, Dc);

    flash_tc<<<dim3(Sc / 128, Hc, Bc), 256, FLASH_SMEM>>>(qb, kb, vb, ab);

    gemm_tc<<<gblk, 512, GEMM_SMEM>>>(ab, Wo, bo, out, Mc, Dc, Dc);
}